// round 10
// baseline (speedup 1.0000x reference)
#include <cuda_runtime.h>
#include <cuda_bf16.h>
#include <math.h>
#include <cstdint>

#define NN 100000
#define NE 1600000
#define RR 4
#define DD 128
#define CC 2
#define NR (NN * RR)                     // 400000 segments
#define SCAN_NBLK ((NR + 1023) / 1024)   // 391
#define TM 64                            // nodes per CTA tile

// ---- scratch (device globals: no allocation allowed in kernel_launch) ----
__device__ float g_h1[(size_t)NN * DD];        // 51.2 MB  layer-1 out (tanh)
__device__ float g_h2[(size_t)NN * DD];        // 51.2 MB  layer-2 out (tanh)
__device__ float g_xw3[(size_t)RR * NN * CC];  // 3.2 MB   layer-3 transformed
__device__ float g_out3[(size_t)NN * CC];      // 0.8 MB   logits accumulator
__device__ int   g_cnt[NR];
__device__ float g_inv[NR];
// CSR (edges sorted by (dst, relation))
__device__ int   g_off[NR + 1];
__device__ int   g_cur[NR];
__device__ int   g_bsum[512];
__device__ int   g_boff[512];
__device__ unsigned g_csr[NE];
// W1,W2 transposed bf16 splits: [layer][r][n_out][k]
__device__ __nv_bfloat16 g_whi[2 * RR * DD * DD];
__device__ __nv_bfloat16 g_wlo[2 * RR * DD * DD];

__device__ __forceinline__ uint32_t smem_u32(const void* p) {
    uint32_t a;
    asm("{ .reg .u64 t; cvta.to.shared.u64 t, %1; cvt.u32.u64 %0, t; }" : "=r"(a) : "l"(p));
    return a;
}
#define BAR_SYNC(id)   asm volatile("bar.sync %0, 256;"   :: "r"(id) : "memory")
#define BAR_ARRIVE(id) asm volatile("bar.arrive %0, 256;" :: "r"(id) : "memory")

// ------------------------------------------------------------------ utils
__global__ void zero_f_kernel(float* p, int n) {
    int i = blockIdx.x * blockDim.x + threadIdx.x;
    int stride = gridDim.x * blockDim.x;
    for (; i < n; i += stride) p[i] = 0.0f;
}
__global__ void zero_i_kernel(int* p, int n) {
    int i = blockIdx.x * blockDim.x + threadIdx.x;
    if (i < n) p[i] = 0;
}
__global__ void count_kernel(const int* __restrict__ ei, const int* __restrict__ et) {
    int e = blockIdx.x * blockDim.x + threadIdx.x;
    if (e < NE) atomicAdd(&g_cnt[ei[NE + e] * RR + et[e]], 1);
}
__global__ void inv_kernel() {      // also zeroes the placement cursors
    int i = blockIdx.x * blockDim.x + threadIdx.x;
    if (i < NR) {
        g_inv[i] = 1.0f / fmaxf((float)g_cnt[i], 1.0f);
        g_cur[i] = 0;
    }
}

// ---------------------------------------------- CSR build: scan + placement
__global__ void k_blocksum() {
    __shared__ int sh[256];
    int b = blockIdx.x, t = threadIdx.x;
    int base = b * 1024 + t * 4;
    int s = 0;
#pragma unroll
    for (int j = 0; j < 4; j++) {
        int idx = base + j;
        if (idx < NR) s += g_cnt[idx];
    }
    sh[t] = s;
    __syncthreads();
    for (int o = 128; o > 0; o >>= 1) {
        if (t < o) sh[t] += sh[t + o];
        __syncthreads();
    }
    if (t == 0) g_bsum[b] = sh[0];
}
__global__ void k_scanb(int nb) {
    if (threadIdx.x == 0) {
        int run = 0;
        for (int i = 0; i < nb; i++) { g_boff[i] = run; run += g_bsum[i]; }
        g_off[NR] = run;
    }
}
__global__ void k_scanlocal() {
    __shared__ int sh[256];
    int b = blockIdx.x, t = threadIdx.x;
    int base = b * 1024 + t * 4;
    int c[4], s = 0;
#pragma unroll
    for (int j = 0; j < 4; j++) {
        int idx = base + j;
        c[j] = (idx < NR) ? g_cnt[idx] : 0;
        s += c[j];
    }
    sh[t] = s;
    __syncthreads();
    for (int o = 1; o < 256; o <<= 1) {
        int u = (t >= o) ? sh[t - o] : 0;
        __syncthreads();
        sh[t] += u;
        __syncthreads();
    }
    int run = g_boff[b] + sh[t] - s;
#pragma unroll
    for (int j = 0; j < 4; j++) {
        int idx = base + j;
        if (idx < NR) { g_off[idx] = run; run += c[j]; }
    }
}
__global__ void place_kernel(const int* __restrict__ ei, const int* __restrict__ et) {
    int e = blockIdx.x * blockDim.x + threadIdx.x;
    if (e >= NE) return;
    int src = ei[e], d = ei[NE + e], r = et[e];
    int seg = d * RR + r;
    int pos = g_off[seg] + atomicAdd(&g_cur[seg], 1);
    g_csr[pos] = (unsigned)src;
}

// W [R,K,N] fp32 -> transposed bf16 splits at [layer][r][n][k]
__global__ void convert_w_kernel(const float* __restrict__ W, int layer) {
    int i = blockIdx.x * blockDim.x + threadIdx.x;
    if (i >= RR * DD * DD) return;
    int r = i / (DD * DD), rem = i % (DD * DD);
    int n = rem / DD, k = rem % DD;
    float v = W[(r * DD + k) * DD + n];
    __nv_bfloat16 hi = __float2bfloat16_rn(v);
    __nv_bfloat16 lo = __float2bfloat16_rn(v - __bfloat162float(hi));
    g_whi[layer * RR * DD * DD + i] = hi;
    g_wlo[layer * RR * DD * DD + i] = lo;
}

// ===================== fused gather + GEMM, warp-specialized =====================
// OUT[n,:] = tanh( sum_r mean_{src in seg(n,r)} X[src,:] @ W_r )
// CTA tile: TM=64 nodes x 128 out-cols. Warps 4-7 produce (gather-mean + bf16 split,
// W tile copy) into a 2-stage smem ring; warps 0-3 consume via 3-pass split HMMA
// with register accumulation over relations; tanh fused in epilogue.
#define RSTRIDE 272                      // 136 bf16 per padded row
#define A_TILE (TM * RSTRIDE)            // 17408
#define W_TILE (DD * RSTRIDE)            // 34816
#define ST_A_HI 0
#define ST_A_LO A_TILE
#define ST_W_HI (2 * A_TILE)
#define ST_W_LO (2 * A_TILE + W_TILE)
#define STAGE_BYTES (2 * A_TILE + 2 * W_TILE)   // 104448
#define FUSED_SMEM (2 * STAGE_BYTES)            // 208896

__global__ void __launch_bounds__(256, 1)
fused_kernel(int layer, const float* __restrict__ X, float* __restrict__ OUT) {
    extern __shared__ char smem[];
    const uint32_t sbase = smem_u32(smem);
    const int tid = threadIdx.x;
    const int wid = tid >> 5, lane = tid & 31;
    const int n0 = blockIdx.x * TM;

    if (wid >= 4) {
        // ---------------- producers ----------------
        const int ptid = tid - 128;          // 0..127
        const int pw = wid - 4;              // 0..3
        const float4* x4 = reinterpret_cast<const float4*>(X);
        for (int r = 0; r < RR; r++) {
            const int s = r & 1;
            char* stg = smem + s * STAGE_BYTES;
            if (r >= 2) BAR_SYNC(3 + s);     // wait consumer freed stage
            // W tile copy (coalesced, L2-resident)
            const __nv_bfloat16* wh = g_whi + ((size_t)layer * RR + r) * DD * DD;
            const __nv_bfloat16* wl = g_wlo + ((size_t)layer * RR + r) * DD * DD;
            for (int u = ptid; u < 2048; u += 128) {
                int row = u >> 4, col = (u & 15) * 8;
                uint32_t off = (uint32_t)(row * RSTRIDE + col * 2);
                *reinterpret_cast<uint4*>(stg + ST_W_HI + off) =
                    *reinterpret_cast<const uint4*>(wh + (size_t)row * DD + col);
                *reinterpret_cast<uint4*>(stg + ST_W_LO + off) =
                    *reinterpret_cast<const uint4*>(wl + (size_t)row * DD + col);
            }
            // A gather-mean: warp per node, 16 nodes per warp
            for (int i = 0; i < 16; i++) {
                int rowl = pw * 16 + i;
                int n = n0 + rowl;
                uint2 hp = make_uint2(0, 0), lp = make_uint2(0, 0);
                if (n < NN) {
                    int seg = n * RR + r;
                    int s0 = g_off[seg], e0 = g_off[seg + 1];
                    float4 a0 = make_float4(0.f, 0.f, 0.f, 0.f);
                    float4 a1 = make_float4(0.f, 0.f, 0.f, 0.f);
                    int j = s0;
                    for (; j + 1 < e0; j += 2) {
                        float4 v0 = x4[(size_t)g_csr[j] * 32 + lane];
                        float4 v1 = x4[(size_t)g_csr[j + 1] * 32 + lane];
                        a0.x += v0.x; a0.y += v0.y; a0.z += v0.z; a0.w += v0.w;
                        a1.x += v1.x; a1.y += v1.y; a1.z += v1.z; a1.w += v1.w;
                    }
                    if (j < e0) {
                        float4 v0 = x4[(size_t)g_csr[j] * 32 + lane];
                        a0.x += v0.x; a0.y += v0.y; a0.z += v0.z; a0.w += v0.w;
                    }
                    float iv = g_inv[seg];
                    float m0 = (a0.x + a1.x) * iv, m1 = (a0.y + a1.y) * iv;
                    float m2 = (a0.z + a1.z) * iv, m3 = (a0.w + a1.w) * iv;
                    __nv_bfloat16 h0 = __float2bfloat16_rn(m0);
                    __nv_bfloat16 h1 = __float2bfloat16_rn(m1);
                    __nv_bfloat16 h2 = __float2bfloat16_rn(m2);
                    __nv_bfloat16 h3 = __float2bfloat16_rn(m3);
                    __nv_bfloat16 l0 = __float2bfloat16_rn(m0 - __bfloat162float(h0));
                    __nv_bfloat16 l1 = __float2bfloat16_rn(m1 - __bfloat162float(h1));
                    __nv_bfloat16 l2 = __float2bfloat16_rn(m2 - __bfloat162float(h2));
                    __nv_bfloat16 l3 = __float2bfloat16_rn(m3 - __bfloat162float(h3));
                    hp.x = ((uint32_t)__bfloat16_as_ushort(h1) << 16) | __bfloat16_as_ushort(h0);
                    hp.y = ((uint32_t)__bfloat16_as_ushort(h3) << 16) | __bfloat16_as_ushort(h2);
                    lp.x = ((uint32_t)__bfloat16_as_ushort(l1) << 16) | __bfloat16_as_ushort(l0);
                    lp.y = ((uint32_t)__bfloat16_as_ushort(l3) << 16) | __bfloat16_as_ushort(l2);
                }
                uint32_t off = (uint32_t)(rowl * RSTRIDE + lane * 8);
                *reinterpret_cast<uint2*>(stg + ST_A_HI + off) = hp;
                *reinterpret_cast<uint2*>(stg + ST_A_LO + off) = lp;
            }
            __threadfence_block();
            BAR_ARRIVE(1 + s);               // stage full
        }
    } else {
        // ---------------- consumers ----------------
        const int wn = wid * 32;
        float acc[4][4][4];
#pragma unroll
        for (int mi = 0; mi < 4; mi++)
#pragma unroll
            for (int ni = 0; ni < 4; ni++)
#pragma unroll
                for (int q = 0; q < 4; q++) acc[mi][ni][q] = 0.0f;

        const int a_row = (lane & 15);
        const int a_kof = (lane >> 4) * 8;
        const int b_row = ((lane >> 4) << 3) + (lane & 7);
        const int b_kof = ((lane >> 3) & 1) * 8;

        for (int r = 0; r < RR; r++) {
            const int s = r & 1;
            const uint32_t stg = sbase + s * STAGE_BYTES;
            BAR_SYNC(1 + s);                 // wait stage full
#pragma unroll
            for (int pass = 0; pass < 3; pass++) {
                const uint32_t aB = stg + ((pass == 2) ? ST_A_LO : ST_A_HI);
                const uint32_t bB = stg + ((pass == 1) ? ST_W_LO : ST_W_HI);
#pragma unroll
                for (int ks = 0; ks < 8; ks++) {
                    const int k0 = ks * 16;
                    uint32_t a[4][4];
#pragma unroll
                    for (int mi = 0; mi < 4; mi++) {
                        uint32_t addr = aB + (uint32_t)((mi * 16 + a_row) * RSTRIDE +
                                                        (k0 + a_kof) * 2);
                        asm volatile("ldmatrix.sync.aligned.m8n8.x4.shared.b16 {%0,%1,%2,%3}, [%4];"
                                     : "=r"(a[mi][0]), "=r"(a[mi][1]), "=r"(a[mi][2]), "=r"(a[mi][3])
                                     : "r"(addr));
                    }
                    uint32_t b[2][4];
#pragma unroll
                    for (int nb = 0; nb < 2; nb++) {
                        uint32_t addr = bB + (uint32_t)((wn + nb * 16 + b_row) * RSTRIDE +
                                                        (k0 + b_kof) * 2);
                        asm volatile("ldmatrix.sync.aligned.m8n8.x4.shared.b16 {%0,%1,%2,%3}, [%4];"
                                     : "=r"(b[nb][0]), "=r"(b[nb][1]), "=r"(b[nb][2]), "=r"(b[nb][3])
                                     : "r"(addr));
                    }
#pragma unroll
                    for (int mi = 0; mi < 4; mi++) {
#pragma unroll
                        for (int ni = 0; ni < 4; ni++) {
                            uint32_t b0 = b[ni >> 1][(ni & 1) ? 2 : 0];
                            uint32_t b1 = b[ni >> 1][(ni & 1) ? 3 : 1];
                            asm volatile(
                                "mma.sync.aligned.m16n8k16.row.col.f32.bf16.bf16.f32 "
                                "{%0,%1,%2,%3}, {%4,%5,%6,%7}, {%8,%9}, {%0,%1,%2,%3};"
                                : "+f"(acc[mi][ni][0]), "+f"(acc[mi][ni][1]),
                                  "+f"(acc[mi][ni][2]), "+f"(acc[mi][ni][3])
                                : "r"(a[mi][0]), "r"(a[mi][1]), "r"(a[mi][2]), "r"(a[mi][3]),
                                  "r"(b0), "r"(b1));
                        }
                    }
                }
            }
            if (r < 2) BAR_ARRIVE(3 + s);    // stage free for reuse
        }

        // epilogue: tanh + fp32 store
        const int gid = lane >> 2, tq = lane & 3;
#pragma unroll
        for (int mi = 0; mi < 4; mi++) {
            int row0 = n0 + mi * 16 + gid;
            int row1 = row0 + 8;
#pragma unroll
            for (int ni = 0; ni < 4; ni++) {
                int col = wn + ni * 8 + tq * 2;
                if (row0 < NN)
                    *reinterpret_cast<float2*>(OUT + (size_t)row0 * DD + col) =
                        make_float2(tanhf(acc[mi][ni][0]), tanhf(acc[mi][ni][1]));
                if (row1 < NN)
                    *reinterpret_cast<float2*>(OUT + (size_t)row1 * DD + col) =
                        make_float2(tanhf(acc[mi][ni][2]), tanhf(acc[mi][ni][3]));
            }
        }
    }
}

// ---------------------------------------------- layer 3 (input already tanh'd)
__global__ void transform3_kernel(const float* __restrict__ H, const float* __restrict__ W3) {
    __shared__ float hs[32 * DD];
    __shared__ float ws[RR * DD * CC];
    const int t  = threadIdx.x;  // 128
    const int n0 = blockIdx.x * 32;

    for (int i = t; i < RR * DD * CC; i += 128) ws[i] = W3[i];
    for (int i = t; i < 32 * DD; i += 128) {
        int row = i >> 7, col = i & 127;
        int n = n0 + row;
        hs[i] = (n < NN) ? H[(size_t)n * DD + col] : 0.0f;
    }
    __syncthreads();

    for (int o = t; o < 32 * RR * CC; o += 128) {
        int node = o >> 3, rc = o & 7;
        int r = rc >> 1, c = rc & 1;
        float acc = 0.0f;
#pragma unroll 8
        for (int k = 0; k < DD; k++)
            acc = fmaf(hs[node * DD + k], ws[(r * DD + k) * CC + c], acc);
        int n = n0 + node;
        if (n < NN) g_xw3[((size_t)r * NN + n) * CC + c] = acc;
    }
}

__global__ void scatter3_kernel(const int* __restrict__ ei, const int* __restrict__ et) {
    int e = blockIdx.x * blockDim.x + threadIdx.x;
    if (e >= NE) return;
    int s = ei[e], d = ei[NE + e], ty = et[e];
    float iv = g_inv[d * RR + ty];
    float2 v = *reinterpret_cast<const float2*>(&g_xw3[((size_t)ty * NN + s) * CC]);
    float* o = &g_out3[(size_t)d * CC];
    asm volatile("red.global.add.v2.f32 [%0], {%1, %2};"
                 :: "l"(o), "f"(v.x * iv), "f"(v.y * iv) : "memory");
}

__global__ void softmax_kernel(float* __restrict__ out, int out_size) {
    int n = blockIdx.x * blockDim.x + threadIdx.x;
    if (n >= NN) return;
    float a = g_out3[n * 2], b = g_out3[n * 2 + 1];
    float m = fmaxf(a, b);
    float ea = __expf(a - m), eb = __expf(b - m);
    float s = 1.0f / (ea + eb);
    out[n * 2]     = ea * s;
    out[n * 2 + 1] = eb * s;
    if (out_size >= 2 * NN * CC) {
        out[NN * CC + n * 2]     = a;
        out[NN * CC + n * 2 + 1] = b;
    }
}

// ------------------------------------------------------------------ launch
extern "C" void kernel_launch(void* const* d_in, const int* in_sizes, int n_in,
                              void* d_out, int out_size) {
    const float* x  = (const float*)d_in[0];
    const int*   ei = (const int*)d_in[1];
    const int*   et = (const int*)d_in[2];
    const float* W1 = (const float*)d_in[3];
    const float* W2 = (const float*)d_in[4];
    const float* W3 = (const float*)d_in[5];
    float* out = (float*)d_out;

    static int attr_set = 0;
    if (!attr_set) {
        cudaFuncSetAttribute(fused_kernel,
                             cudaFuncAttributeMaxDynamicSharedMemorySize, FUSED_SMEM);
        attr_set = 1;
    }

    float *p_h1, *p_h2, *p_out3;
    int* p_cnt;
    cudaGetSymbolAddress((void**)&p_h1, g_h1);
    cudaGetSymbolAddress((void**)&p_h2, g_h2);
    cudaGetSymbolAddress((void**)&p_out3, g_out3);
    cudaGetSymbolAddress((void**)&p_cnt, g_cnt);

    const int fgrid = (NN + TM - 1) / TM;            // 1563

    // counts -> inv(+cursor zero), CSR offsets + placement
    zero_i_kernel<<<(NR + 255) / 256, 256>>>(p_cnt, NR);
    count_kernel<<<(NE + 255) / 256, 256>>>(ei, et);
    inv_kernel<<<(NR + 255) / 256, 256>>>();
    k_blocksum<<<SCAN_NBLK, 256>>>();
    k_scanb<<<1, 32>>>(SCAN_NBLK);
    k_scanlocal<<<SCAN_NBLK, 256>>>();
    place_kernel<<<(NE + 255) / 256, 256>>>(ei, et);

    // weight splits
    convert_w_kernel<<<(RR * DD * DD + 255) / 256, 256>>>(W1, 0);
    convert_w_kernel<<<(RR * DD * DD + 255) / 256, 256>>>(W2, 1);

    // layer 1 + 2: fused gather-mean + GEMM (+tanh)
    fused_kernel<<<fgrid, 256, FUSED_SMEM>>>(0, x, p_h1);
    fused_kernel<<<fgrid, 256, FUSED_SMEM>>>(1, p_h1, p_h2);

    // layer 3
    transform3_kernel<<<(NN + 31) / 32, 128>>>(p_h2, W3);
    zero_f_kernel<<<(NN * CC + 255) / 256, 256>>>(p_out3, NN * CC);
    scatter3_kernel<<<(NE + 255) / 256, 256>>>(ei, et);

    softmax_kernel<<<(NN + 255) / 256, 256>>>(out, out_size);
}

// round 11
// speedup vs baseline: 2.4662x; 2.4662x over previous
#include <cuda_runtime.h>
#include <cuda_bf16.h>
#include <math.h>
#include <cstdint>

#define NN 100000
#define NE 1600000
#define RR 4
#define DD 128
#define CC 2
#define NR (NN * RR)                     // 400000 segments
#define SCAN_NBLK ((NR + 1023) / 1024)   // 391

// ---- scratch (device globals: no allocation allowed in kernel_launch) ----
__device__ float g_h1[(size_t)NN * DD];        // 51.2 MB
__device__ float g_h2[(size_t)NN * DD];        // 51.2 MB
__device__ float g_xw3[(size_t)RR * NN * CC];  // 3.2 MB
__device__ float g_out3[(size_t)NN * CC];      // 0.8 MB
__device__ int   g_cnt[NR];
__device__ float g_inv[NR];
__device__ int   g_off[NR + 1];
__device__ int   g_cur[NR];
__device__ int   g_bsum[512];
__device__ int   g_boff[512];
__device__ unsigned g_csr[NE];
// aggregated means, pre-split bf16 hi/lo: layout [seg][128], seg = n*RR + r
__device__ __align__(16) __nv_bfloat16 g_ahi[(size_t)NR * DD];   // 102.4 MB
__device__ __align__(16) __nv_bfloat16 g_alo[(size_t)NR * DD];   // 102.4 MB
__device__ __align__(16) __nv_bfloat16 g_whi[2 * RR * DD * DD];
__device__ __align__(16) __nv_bfloat16 g_wlo[2 * RR * DD * DD];

__device__ __forceinline__ uint32_t smem_u32(const void* p) {
    uint32_t a;
    asm("{ .reg .u64 t; cvta.to.shared.u64 t, %1; cvt.u32.u64 %0, t; }" : "=r"(a) : "l"(p));
    return a;
}
__device__ __forceinline__ void cp16(uint32_t dst, const void* src, int sz) {
    asm volatile("cp.async.cg.shared.global [%0], [%1], 16, %2;"
                 :: "r"(dst), "l"(src), "r"(sz) : "memory");
}
__device__ __forceinline__ void cp_commit() {
    asm volatile("cp.async.commit_group;" ::: "memory");
}
template <int N> __device__ __forceinline__ void cp_wait() {
    asm volatile("cp.async.wait_group %0;" :: "n"(N) : "memory");
}

// ------------------------------------------------------------------ utils
__global__ void zero_f_kernel(float* p, int n) {
    int i = blockIdx.x * blockDim.x + threadIdx.x;
    int stride = gridDim.x * blockDim.x;
    for (; i < n; i += stride) p[i] = 0.0f;
}
__global__ void zero_i_kernel(int* p, int n) {
    int i = blockIdx.x * blockDim.x + threadIdx.x;
    if (i < n) p[i] = 0;
}
__global__ void count_kernel(const int* __restrict__ ei, const int* __restrict__ et) {
    int e = blockIdx.x * blockDim.x + threadIdx.x;
    if (e < NE) atomicAdd(&g_cnt[ei[NE + e] * RR + et[e]], 1);
}
__global__ void inv_kernel() {      // also zeroes the placement cursors
    int i = blockIdx.x * blockDim.x + threadIdx.x;
    if (i < NR) {
        g_inv[i] = 1.0f / fmaxf((float)g_cnt[i], 1.0f);
        g_cur[i] = 0;
    }
}

// ---------------------------------------------- CSR build: scan + placement
__global__ void k_blocksum() {
    __shared__ int sh[256];
    int b = blockIdx.x, t = threadIdx.x;
    int base = b * 1024 + t * 4;
    int s = 0;
#pragma unroll
    for (int j = 0; j < 4; j++) {
        int idx = base + j;
        if (idx < NR) s += g_cnt[idx];
    }
    sh[t] = s;
    __syncthreads();
    for (int o = 128; o > 0; o >>= 1) {
        if (t < o) sh[t] += sh[t + o];
        __syncthreads();
    }
    if (t == 0) g_bsum[b] = sh[0];
}
__global__ void k_scanb(int nb) {
    if (threadIdx.x == 0) {
        int run = 0;
        for (int i = 0; i < nb; i++) { g_boff[i] = run; run += g_bsum[i]; }
        g_off[NR] = run;
    }
}
__global__ void k_scanlocal() {
    __shared__ int sh[256];
    int b = blockIdx.x, t = threadIdx.x;
    int base = b * 1024 + t * 4;
    int c[4], s = 0;
#pragma unroll
    for (int j = 0; j < 4; j++) {
        int idx = base + j;
        c[j] = (idx < NR) ? g_cnt[idx] : 0;
        s += c[j];
    }
    sh[t] = s;
    __syncthreads();
    for (int o = 1; o < 256; o <<= 1) {
        int u = (t >= o) ? sh[t - o] : 0;
        __syncthreads();
        sh[t] += u;
        __syncthreads();
    }
    int run = g_boff[b] + sh[t] - s;
#pragma unroll
    for (int j = 0; j < 4; j++) {
        int idx = base + j;
        if (idx < NR) { g_off[idx] = run; run += c[j]; }
    }
}
__global__ void place_kernel(const int* __restrict__ ei, const int* __restrict__ et) {
    int e = blockIdx.x * blockDim.x + threadIdx.x;
    if (e >= NE) return;
    int src = ei[e], d = ei[NE + e], r = et[e];
    int seg = d * RR + r;
    int pos = g_off[seg] + atomicAdd(&g_cur[seg], 1);
    g_csr[pos] = (unsigned)src;
}

// W [R,K,N] fp32 -> transposed bf16 splits at [layer][r][n][k]
__global__ void convert_w_kernel(const float* __restrict__ W, int layer) {
    int i = blockIdx.x * blockDim.x + threadIdx.x;
    if (i >= RR * DD * DD) return;
    int r = i / (DD * DD), rem = i % (DD * DD);
    int n = rem / DD, k = rem % DD;
    float v = W[(r * DD + k) * DD + n];
    __nv_bfloat16 hi = __float2bfloat16_rn(v);
    __nv_bfloat16 lo = __float2bfloat16_rn(v - __bfloat162float(hi));
    g_whi[layer * RR * DD * DD + i] = hi;
    g_wlo[layer * RR * DD * DD + i] = lo;
}

// ------------------------------------- gather-mean: one warp per (node, relation)
// A[seg][:] = inv * sum(x[src]); split to bf16 hi/lo. 4-deep unrolled for MLP.
__global__ void __launch_bounds__(256) gather_kernel(const float* __restrict__ X) {
    int gw = (blockIdx.x * blockDim.x + threadIdx.x) >> 5;
    int lane = threadIdx.x & 31;
    if (gw >= NR) return;
    const float4* x4 = reinterpret_cast<const float4*>(X);

    int s = g_off[gw], e = g_off[gw + 1];
    float4 a0 = make_float4(0.f, 0.f, 0.f, 0.f);
    float4 a1 = make_float4(0.f, 0.f, 0.f, 0.f);
    float4 a2 = make_float4(0.f, 0.f, 0.f, 0.f);
    float4 a3 = make_float4(0.f, 0.f, 0.f, 0.f);
    int j = s;
    for (; j + 3 < e; j += 4) {
        float4 v0 = x4[(size_t)g_csr[j]     * 32 + lane];
        float4 v1 = x4[(size_t)g_csr[j + 1] * 32 + lane];
        float4 v2 = x4[(size_t)g_csr[j + 2] * 32 + lane];
        float4 v3 = x4[(size_t)g_csr[j + 3] * 32 + lane];
        a0.x += v0.x; a0.y += v0.y; a0.z += v0.z; a0.w += v0.w;
        a1.x += v1.x; a1.y += v1.y; a1.z += v1.z; a1.w += v1.w;
        a2.x += v2.x; a2.y += v2.y; a2.z += v2.z; a2.w += v2.w;
        a3.x += v3.x; a3.y += v3.y; a3.z += v3.z; a3.w += v3.w;
    }
    for (; j < e; j++) {
        float4 v0 = x4[(size_t)g_csr[j] * 32 + lane];
        a0.x += v0.x; a0.y += v0.y; a0.z += v0.z; a0.w += v0.w;
    }
    float iv = g_inv[gw];
    float m0 = ((a0.x + a1.x) + (a2.x + a3.x)) * iv;
    float m1 = ((a0.y + a1.y) + (a2.y + a3.y)) * iv;
    float m2 = ((a0.z + a1.z) + (a2.z + a3.z)) * iv;
    float m3 = ((a0.w + a1.w) + (a2.w + a3.w)) * iv;

    __nv_bfloat16 h0 = __float2bfloat16_rn(m0);
    __nv_bfloat16 h1 = __float2bfloat16_rn(m1);
    __nv_bfloat16 h2 = __float2bfloat16_rn(m2);
    __nv_bfloat16 h3 = __float2bfloat16_rn(m3);
    __nv_bfloat16 l0 = __float2bfloat16_rn(m0 - __bfloat162float(h0));
    __nv_bfloat16 l1 = __float2bfloat16_rn(m1 - __bfloat162float(h1));
    __nv_bfloat16 l2 = __float2bfloat16_rn(m2 - __bfloat162float(h2));
    __nv_bfloat16 l3 = __float2bfloat16_rn(m3 - __bfloat162float(h3));
    uint2 hp, lp;
    hp.x = ((uint32_t)__bfloat16_as_ushort(h1) << 16) | __bfloat16_as_ushort(h0);
    hp.y = ((uint32_t)__bfloat16_as_ushort(h3) << 16) | __bfloat16_as_ushort(h2);
    lp.x = ((uint32_t)__bfloat16_as_ushort(l1) << 16) | __bfloat16_as_ushort(l0);
    lp.y = ((uint32_t)__bfloat16_as_ushort(l3) << 16) | __bfloat16_as_ushort(l2);
    size_t base = (size_t)gw * DD + lane * 4;
    *reinterpret_cast<uint2*>(g_ahi + base) = hp;
    *reinterpret_cast<uint2*>(g_alo + base) = lp;
}

// ------------------------------------------- GEMM: h = tanh(sum_r A_r @ W_r)
// 128x128 tile per CTA; cp.async double-buffered A tiles across relations.
// smem layout: Astage0(hi|lo) | Astage1(hi|lo) | W(hi|lo)  = 208896 B
#define SB 272                           // padded row stride in bytes (136 bf16)
#define HTILE (128 * SB)                 // 34816 (one hi or lo tile)
#define ASTAGE (2 * HTILE)               // 69632
#define OFF_W  (2 * ASTAGE)              // 139264
#define GEMM_SMEM (2 * ASTAGE + 2 * HTILE)   // 208896

__global__ void __launch_bounds__(256, 1) gemm_kernel(int layer, float* __restrict__ OUT) {
    extern __shared__ char smem[];
    const uint32_t sbase = smem_u32(smem);
    const int tid = threadIdx.x;
    const int wid = tid >> 5, lane = tid & 31;
    const int n0 = blockIdx.x * 128;

    const int wm = (wid & 1) * 64;
    const int wn = (wid >> 1) * 32;

    float acc[4][4][4];
#pragma unroll
    for (int mi = 0; mi < 4; mi++)
#pragma unroll
        for (int ni = 0; ni < 4; ni++)
#pragma unroll
            for (int q = 0; q < 4; q++) acc[mi][ni][q] = 0.0f;

    const int a_row = (lane & 15);
    const int a_kof = (lane >> 4) * 8;
    const int b_row = ((lane >> 4) << 3) + (lane & 7);
    const int b_kof = ((lane >> 3) & 1) * 8;

    // prefetch of relation r's A tile into stage s
    auto prefetch_A = [&](int r, int s) {
        uint32_t dst0 = sbase + s * ASTAGE;
#pragma unroll
        for (int it = 0; it < 8; it++) {
            int u = tid + it * 256;                 // 0..2047
            int row = u >> 4, col = (u & 15) * 8;
            int n = n0 + row;
            int ok = (n < NN);
            size_t ab = ((size_t)(ok ? n : 0) * RR + r) * DD + col;
            uint32_t d = dst0 + (uint32_t)(row * SB + col * 2);
            cp16(d,         g_ahi + ab, ok ? 16 : 0);
            cp16(d + HTILE, g_alo + ab, ok ? 16 : 0);
        }
        cp_commit();
    };

    prefetch_A(0, 0);

    for (int r = 0; r < RR; r++) {
        if (r < RR - 1) prefetch_A(r + 1, (r + 1) & 1);
        // W tile (L2-hot): regular copy; previous iteration's reads done (syncthreads below)
        const __nv_bfloat16* wh = g_whi + ((size_t)layer * RR + r) * DD * DD;
        const __nv_bfloat16* wl = g_wlo + ((size_t)layer * RR + r) * DD * DD;
#pragma unroll
        for (int it = 0; it < 8; it++) {
            int u = tid + it * 256;
            int row = u >> 4, col = (u & 15) * 8;
            uint32_t off = (uint32_t)(row * SB + col * 2);
            *reinterpret_cast<uint4*>(smem + OFF_W + off) =
                *reinterpret_cast<const uint4*>(wh + (size_t)row * DD + col);
            *reinterpret_cast<uint4*>(smem + OFF_W + HTILE + off) =
                *reinterpret_cast<const uint4*>(wl + (size_t)row * DD + col);
        }
        if (r < RR - 1) cp_wait<1>(); else cp_wait<0>();
        __syncthreads();

        const uint32_t stA = sbase + (r & 1) * ASTAGE;
        const uint32_t stW = sbase + OFF_W;
#pragma unroll
        for (int pass = 0; pass < 3; pass++) {
            const uint32_t aB = stA + ((pass == 2) ? HTILE : 0);
            const uint32_t bB = stW + ((pass == 1) ? HTILE : 0);
#pragma unroll
            for (int ks = 0; ks < 8; ks++) {
                const int k0 = ks * 16;
                uint32_t a[4][4];
#pragma unroll
                for (int mi = 0; mi < 4; mi++) {
                    uint32_t addr = aB + (uint32_t)((wm + mi * 16 + a_row) * SB +
                                                    (k0 + a_kof) * 2);
                    asm volatile("ldmatrix.sync.aligned.m8n8.x4.shared.b16 {%0,%1,%2,%3}, [%4];"
                                 : "=r"(a[mi][0]), "=r"(a[mi][1]), "=r"(a[mi][2]), "=r"(a[mi][3])
                                 : "r"(addr));
                }
                uint32_t b[2][4];
#pragma unroll
                for (int nb = 0; nb < 2; nb++) {
                    uint32_t addr = bB + (uint32_t)((wn + nb * 16 + b_row) * SB +
                                                    (k0 + b_kof) * 2);
                    asm volatile("ldmatrix.sync.aligned.m8n8.x4.shared.b16 {%0,%1,%2,%3}, [%4];"
                                 : "=r"(b[nb][0]), "=r"(b[nb][1]), "=r"(b[nb][2]), "=r"(b[nb][3])
                                 : "r"(addr));
                }
#pragma unroll
                for (int mi = 0; mi < 4; mi++) {
#pragma unroll
                    for (int ni = 0; ni < 4; ni++) {
                        uint32_t b0 = b[ni >> 1][(ni & 1) ? 2 : 0];
                        uint32_t b1 = b[ni >> 1][(ni & 1) ? 3 : 1];
                        asm volatile(
                            "mma.sync.aligned.m16n8k16.row.col.f32.bf16.bf16.f32 "
                            "{%0,%1,%2,%3}, {%4,%5,%6,%7}, {%8,%9}, {%0,%1,%2,%3};"
                            : "+f"(acc[mi][ni][0]), "+f"(acc[mi][ni][1]),
                              "+f"(acc[mi][ni][2]), "+f"(acc[mi][ni][3])
                            : "r"(a[mi][0]), "r"(a[mi][1]), "r"(a[mi][2]), "r"(a[mi][3]),
                              "r"(b0), "r"(b1));
                    }
                }
            }
        }
        __syncthreads();   // protect W (and A stage reuse) before next iteration's stores
    }

    // ---- epilogue: tanh + write fp32 ----
    const int gid = lane >> 2, tq = lane & 3;
#pragma unroll
    for (int mi = 0; mi < 4; mi++) {
        int row0 = n0 + wm + mi * 16 + gid;
        int row1 = row0 + 8;
#pragma unroll
        for (int ni = 0; ni < 4; ni++) {
            int col = wn + ni * 8 + tq * 2;
            if (row0 < NN)
                *reinterpret_cast<float2*>(OUT + (size_t)row0 * DD + col) =
                    make_float2(tanhf(acc[mi][ni][0]), tanhf(acc[mi][ni][1]));
            if (row1 < NN)
                *reinterpret_cast<float2*>(OUT + (size_t)row1 * DD + col) =
                    make_float2(tanhf(acc[mi][ni][2]), tanhf(acc[mi][ni][3]));
        }
    }
}

// ---------------------------------------------- layer 3 (input already tanh'd)
__global__ void transform3_kernel(const float* __restrict__ H, const float* __restrict__ W3) {
    __shared__ float hs[32 * DD];
    __shared__ float ws[RR * DD * CC];
    const int t  = threadIdx.x;  // 128
    const int n0 = blockIdx.x * 32;

    for (int i = t; i < RR * DD * CC; i += 128) ws[i] = W3[i];
    for (int i = t; i < 32 * DD; i += 128) {
        int row = i >> 7, col = i & 127;
        int n = n0 + row;
        hs[i] = (n < NN) ? H[(size_t)n * DD + col] : 0.0f;
    }
    __syncthreads();

    for (int o = t; o < 32 * RR * CC; o += 128) {
        int node = o >> 3, rc = o & 7;
        int r = rc >> 1, c = rc & 1;
        float acc = 0.0f;
#pragma unroll 8
        for (int k = 0; k < DD; k++)
            acc = fmaf(hs[node * DD + k], ws[(r * DD + k) * CC + c], acc);
        int n = n0 + node;
        if (n < NN) g_xw3[((size_t)r * NN + n) * CC + c] = acc;
    }
}

__global__ void scatter3_kernel(const int* __restrict__ ei, const int* __restrict__ et) {
    int e = blockIdx.x * blockDim.x + threadIdx.x;
    if (e >= NE) return;
    int s = ei[e], d = ei[NE + e], ty = et[e];
    float iv = g_inv[d * RR + ty];
    float2 v = *reinterpret_cast<const float2*>(&g_xw3[((size_t)ty * NN + s) * CC]);
    float* o = &g_out3[(size_t)d * CC];
    asm volatile("red.global.add.v2.f32 [%0], {%1, %2};"
                 :: "l"(o), "f"(v.x * iv), "f"(v.y * iv) : "memory");
}

__global__ void softmax_kernel(float* __restrict__ out, int out_size) {
    int n = blockIdx.x * blockDim.x + threadIdx.x;
    if (n >= NN) return;
    float a = g_out3[n * 2], b = g_out3[n * 2 + 1];
    float m = fmaxf(a, b);
    float ea = __expf(a - m), eb = __expf(b - m);
    float s = 1.0f / (ea + eb);
    out[n * 2]     = ea * s;
    out[n * 2 + 1] = eb * s;
    if (out_size >= 2 * NN * CC) {
        out[NN * CC + n * 2]     = a;
        out[NN * CC + n * 2 + 1] = b;
    }
}

// ------------------------------------------------------------------ launch
extern "C" void kernel_launch(void* const* d_in, const int* in_sizes, int n_in,
                              void* d_out, int out_size) {
    const float* x  = (const float*)d_in[0];
    const int*   ei = (const int*)d_in[1];
    const int*   et = (const int*)d_in[2];
    const float* W1 = (const float*)d_in[3];
    const float* W2 = (const float*)d_in[4];
    const float* W3 = (const float*)d_in[5];
    float* out = (float*)d_out;

    static int attr_set = 0;
    if (!attr_set) {
        cudaFuncSetAttribute(gemm_kernel,
                             cudaFuncAttributeMaxDynamicSharedMemorySize, GEMM_SMEM);
        attr_set = 1;
    }

    float *p_h1, *p_h2, *p_out3;
    int* p_cnt;
    cudaGetSymbolAddress((void**)&p_h1, g_h1);
    cudaGetSymbolAddress((void**)&p_h2, g_h2);
    cudaGetSymbolAddress((void**)&p_out3, g_out3);
    cudaGetSymbolAddress((void**)&p_cnt, g_cnt);

    const int gemm_grid = (NN + 127) / 128;            // 782
    const int gath_grid = ((size_t)NR * 32 + 255) / 256;   // 50000

    // counts -> inv(+cursor zero), CSR offsets + placement
    zero_i_kernel<<<(NR + 255) / 256, 256>>>(p_cnt, NR);
    count_kernel<<<(NE + 255) / 256, 256>>>(ei, et);
    inv_kernel<<<(NR + 255) / 256, 256>>>();
    k_blocksum<<<SCAN_NBLK, 256>>>();
    k_scanb<<<1, 32>>>(SCAN_NBLK);
    k_scanlocal<<<SCAN_NBLK, 256>>>();
    place_kernel<<<(NE + 255) / 256, 256>>>(ei, et);

    // weight splits
    convert_w_kernel<<<(RR * DD * DD + 255) / 256, 256>>>(W1, 0);
    convert_w_kernel<<<(RR * DD * DD + 255) / 256, 256>>>(W2, 1);

    // layer 1
    gather_kernel<<<gath_grid, 256>>>(x);
    gemm_kernel<<<gemm_grid, 256, GEMM_SMEM>>>(0, p_h1);

    // layer 2
    gather_kernel<<<gath_grid, 256>>>(p_h1);
    gemm_kernel<<<gemm_grid, 256, GEMM_SMEM>>>(1, p_h2);

    // layer 3
    transform3_kernel<<<(NN + 31) / 32, 128>>>(p_h2, W3);
    zero_f_kernel<<<(NN * CC + 255) / 256, 256>>>(p_out3, NN * CC);
    scatter3_kernel<<<(NE + 255) / 256, 256>>>(ei, et);

    softmax_kernel<<<(NN + 255) / 256, 256>>>(out, out_size);
}